// round 16
// baseline (speedup 1.0000x reference)
#include <cuda_runtime.h>
#include <cuda_fp16.h>
#include <math.h>

#define FEAT 32
#define NA 64
#define NE 32
#define NL 33           // elevation levels L = 0..NE ; quad(L) = levels (L, L+1) incl. poles
#define WARPS 4
#define BLK 128

// Slerp constants (double-evaluated, truncated to fp32):
#define W_AZ        0.09817477315664291f    // (float)(2*pi/64)
#define W_EL        0.09519977867603302f    // (float)(pi/33)
#define INV_SO_AZ   10.20267391204834f      // (float)(1/sin(2*pi/64))
#define INV_SO_EL   10.52004528045654f      // (float)(1/sin(pi/33))
#define INV_W_AZ    10.185916357881302f     // 64/(2*pi)  (binning only)
#define INV_W_EL    10.504226244065093f     // 33/pi      (binning only)
#define PI_F        3.14159274101257324f
#define HPI_F       1.57079637050628662f

// Quad table: for azimuth edge al (columns al, al+1 mod NA) and level q:
// g_quad[2*((al*NL+q)*32 + f)] = left pair {v[L],v[L+1]}, [..+1] = right pair. 8B per feature.
// One (al,q) column = 32 * 8B = 256B (256B-aligned).
__device__ __half2 g_quad[NA * NL * FEAT * 2];

__global__ void prep_kernel(const float* __restrict__ grid,
                            const float* __restrict__ poles) {
    int idx = blockIdx.x * blockDim.x + threadIdx.x;
    if (idx < NA * NL * FEAT) {
        int f = idx & 31;
        int c = idx >> 5;
        int q = c % NL;
        int al = c / NL;
        int ar = (al + 1) & (NA - 1);
        float xl = (q == 0)  ? poles[2 * f]     : grid[(((f << 6) + al) << 5) + (q - 1)];
        float yl = (q == NE) ? poles[2 * f + 1] : grid[(((f << 6) + al) << 5) + q];
        float xr = (q == 0)  ? poles[2 * f]     : grid[(((f << 6) + ar) << 5) + (q - 1)];
        float yr = (q == NE) ? poles[2 * f + 1] : grid[(((f << 6) + ar) << 5) + q];
        g_quad[2 * idx]     = __floats2half2_rn(xl, yl);
        g_quad[2 * idx + 1] = __floats2half2_rn(xr, yr);
    }
}

__global__ void __launch_bounds__(BLK, 11)
interp_kernel(const float* __restrict__ pts,
              float* __restrict__ out, int n) {
    __shared__ float4 s_cf[WARPS][32];        // 4 bilinear coeffs (fp32)
    // fp16 transpose tile: row(p) = 8*(p&3) + (p>>2); 8 uint2 slots + 1 pad.
    // slot s (logical) holds half2 pairs: .x = feats (2s,2s+1), .y = (16+2s,17+2s),
    // stored at physical slot s ^ ((p>>1)&1).
    __shared__ uint2  s_tile[WARPS][32][9];

    const int t    = threadIdx.x;
    const int warp = t >> 5;
    const int lane = t & 31;

    const int base = blockIdx.x * BLK + warp * 32;

    // ---------- Phase 1: analytic binning (no tables, hardcoded constants) --
    // slerp is continuous at every tick, so approximate binning perturbs the
    // result by ~1e-7; base_el = q*omega_el - pi/2 holds for all branches.
    unsigned my_off;
    {
        int ip = base + lane;
        int ic = min(ip, n - 1);
        float az = pts[ic];
        float el = pts[n + ic];

        float u = az + PI_F;                        // [0, 2pi)
        int al = __float2int_rd(u * INV_W_AZ);
        al = min(max(al, 0), NA - 1);
        float theta_a = fmaf(-(float)al, W_AZ, u);
        float w1a = __sinf(W_AZ - theta_a) * INV_SO_AZ;
        float w2a = __sinf(theta_a) * INV_SO_AZ;

        float v = el + HPI_F;                       // [0, pi]
        int q = __float2int_rd(v * INV_W_EL);
        q = min(max(q, 0), NE);
        float theta_e = fmaf(-(float)q, W_EL, v);
        float w1e = __sinf(W_EL - theta_e) * INV_SO_EL;
        float w2e = __sinf(theta_e) * INV_SO_EL;

        // pole rows appear in BOTH azimuth columns -> renormalize that weight
        float s  = w1a + w2a;
        float wx = (q == 0)  ? __fdividef(w1e, s) : w1e;
        float wy = (q == NE) ? __fdividef(w2e, s) : w2e;

        s_cf[warp][lane] = make_float4(wx * w1a, wy * w1a, wx * w2a, wy * w2a);
        my_off = (unsigned)(al * NL + q) << 8;      // byte offset of 256B column
    }
    __syncwarp();

    // ---------- Phase 2: 4 points / iteration, line-local gathers -----------
    // lane = (pi = lane>>3, fq = lane&7): point p = 4i+pi.
    // qa -> features 2fq, 2fq+1 (line 0 of column); qb -> 16+2fq, 17+2fq (line 1).
    const char* __restrict__ gq = (const char*)g_quad;
    const int pi = lane >> 3;
    const int fq = lane & 7;
    const int sx = (pi >> 1) & 1;      // chunk XOR for this writer's points
    const int sl = fq ^ sx;            // physical uint2 slot

#pragma unroll 4
    for (int i = 0; i < 8; ++i) {
        int p = 4 * i + pi;
        unsigned off = __shfl_sync(0xffffffffu, my_off, p);
        float4 cf = s_cf[warp][p];                 // 4 distinct 16B addrs: 1 wf
        const char* cp = gq + off + 16 * fq;
        uint4 qa = *(const uint4*)(cp);            // features 2fq, 2fq+1
        uint4 qb = *(const uint4*)(cp + 128);      // features 16+2fq, 17+2fq

        // compute results sequentially to keep live ranges short
        float2 la = __half22float2(*(const __half2*)&qa.x);
        float2 ra = __half22float2(*(const __half2*)&qa.y);
        float res0 = fmaf(cf.w, ra.y, fmaf(cf.z, ra.x, fmaf(cf.y, la.y, cf.x * la.x)));
        la = __half22float2(*(const __half2*)&qa.z);
        ra = __half22float2(*(const __half2*)&qa.w);
        float res1 = fmaf(cf.w, ra.y, fmaf(cf.z, ra.x, fmaf(cf.y, la.y, cf.x * la.x)));
        __half2 ha = __floats2half2_rn(res0, res1);   // feats 2fq, 2fq+1

        la = __half22float2(*(const __half2*)&qb.x);
        ra = __half22float2(*(const __half2*)&qb.y);
        res0 = fmaf(cf.w, ra.y, fmaf(cf.z, ra.x, fmaf(cf.y, la.y, cf.x * la.x)));
        la = __half22float2(*(const __half2*)&qb.z);
        ra = __half22float2(*(const __half2*)&qb.w);
        res1 = fmaf(cf.w, ra.y, fmaf(cf.z, ra.x, fmaf(cf.y, la.y, cf.x * la.x)));
        __half2 hb = __floats2half2_rn(res0, res1);   // feats 16+2fq, 17+2fq

        int row = 8 * pi + i;                          // row(p) = 8*(p&3) + (p>>2)
        s_tile[warp][row][sl] = make_uint2(*(unsigned*)&ha, *(unsigned*)&hb);
    }
    __syncwarp();

    // ---------- Phase 3: 8x LDS.64 (conflict-free) + unpack + coalesced STG -
    int ip = base + lane;
    if (ip < n) {
        const int row = 8 * (lane & 3) + (lane >> 2);
        const int x   = (lane >> 1) & 1;
        const size_t sn = (size_t)n;
        float* o = out + ip;
#pragma unroll
        for (int m = 0; m < 8; ++m) {
            uint2 v = s_tile[warp][row][m ^ x];
            float2 a = __half22float2(*(const __half2*)&v.x);  // feats 2m, 2m+1
            float2 b = __half22float2(*(const __half2*)&v.y);  // feats 16+2m, 17+2m
            o[(size_t)(2 * m)      * sn] = a.x;
            o[(size_t)(2 * m + 1)  * sn] = a.y;
            o[(size_t)(16 + 2 * m) * sn] = b.x;
            o[(size_t)(17 + 2 * m) * sn] = b.y;
        }
    }
}

extern "C" void kernel_launch(void* const* d_in, const int* in_sizes, int n_in,
                              void* d_out, int out_size) {
    const float* pts   = (const float*)d_in[0];  // (2, N)
    const float* grid  = (const float*)d_in[1];  // (32, 64, 32)
    const float* poles = (const float*)d_in[2];  // (32, 2)
    float* out = (float*)d_out;                  // (32, N)
    int n = in_sizes[0] / 2;

    prep_kernel<<<(NA * NL * FEAT + 255) / 256, 256>>>(grid, poles);
    interp_kernel<<<(n + BLK - 1) / BLK, BLK>>>(pts, out, n);
}

// round 17
// speedup vs baseline: 1.0167x; 1.0167x over previous
#include <cuda_runtime.h>
#include <cuda_fp16.h>
#include <math.h>

#define FEAT 32
#define NA 64
#define NE 32
#define NL 33           // elevation levels L = 0..NE ; quad(L) = levels (L, L+1) incl. poles
#define WARPS 4
#define BLK 128

// Slerp constants (double-evaluated, truncated to fp32):
#define W_AZ        0.09817477315664291f    // (float)(2*pi/64)
#define W_EL        0.09519977867603302f    // (float)(pi/33)
#define INV_SO_AZ   10.20267391204834f      // (float)(1/sin(2*pi/64))
#define INV_SO_EL   10.52004528045654f      // (float)(1/sin(pi/33))
#define INV_W_AZ    10.185916357881302f     // 64/(2*pi)  (binning only)
#define INV_W_EL    10.504226244065093f     // 33/pi      (binning only)
#define PI_F        3.14159274101257324f
#define HPI_F       1.57079637050628662f

// Quad table: for azimuth edge al (columns al, al+1 mod NA) and level q:
// g_quad[2*((al*NL+q)*32 + f)] = left pair {v[L],v[L+1]}, [..+1] = right pair. 8B per feature.
// One (al,q) column = 32 * 8B = 256B (256B-aligned).
__device__ __half2 g_quad[NA * NL * FEAT * 2];

// Prep with coalesced grid reads: idx = f*2112 + c, so consecutive lanes span
// consecutive q (innermost grid dim) -> reads ~3 wf/warp instead of 128.
// Writes scatter (stride 256B), but that's only 32 one-line wavefronts.
__global__ void prep_kernel(const float* __restrict__ grid,
                            const float* __restrict__ poles) {
    int idx = blockIdx.x * blockDim.x + threadIdx.x;
    if (idx < NA * NL * FEAT) {
        int f = idx / (NA * NL);
        int c = idx - f * (NA * NL);
        int al = c / NL;
        int q  = c - al * NL;
        int ar = (al + 1) & (NA - 1);
        const float* gf = grid + (f << 11);           // grid[f][.][.]
        float xl = (q == 0)  ? poles[2 * f]     : gf[(al << 5) + (q - 1)];
        float yl = (q == NE) ? poles[2 * f + 1] : gf[(al << 5) + q];
        float xr = (q == 0)  ? poles[2 * f]     : gf[(ar << 5) + (q - 1)];
        float yr = (q == NE) ? poles[2 * f + 1] : gf[(ar << 5) + q];
        int o = c * FEAT + f;                          // quad slot
        g_quad[2 * o]     = __floats2half2_rn(xl, yl);
        g_quad[2 * o + 1] = __floats2half2_rn(xr, yr);
    }
}

__global__ void __launch_bounds__(BLK, 10)
interp_kernel(const float* __restrict__ pts,
              float* __restrict__ out, int n) {
    __shared__ float4 s_cf[WARPS][32];        // 4 bilinear coeffs (fp32)
    // fp16 transpose tile: row(p) = 8*(p&3) + (p>>2); 8 uint2 slots + 1 pad.
    // slot s (logical) holds half2 pairs: .x = feats (2s,2s+1), .y = (16+2s,17+2s),
    // stored at physical slot s ^ ((p>>1)&1).
    __shared__ uint2  s_tile[WARPS][32][9];

    const int t    = threadIdx.x;
    const int warp = t >> 5;
    const int lane = t & 31;

    const int base = blockIdx.x * BLK + warp * 32;

    // ---------- Phase 1: analytic binning (no tables, hardcoded constants) --
    // slerp is continuous at every tick, so approximate binning perturbs the
    // result by ~1e-7; base_el = q*omega_el - pi/2 holds for all branches.
    unsigned my_off;
    {
        int ip = base + lane;
        int ic = min(ip, n - 1);
        float az = pts[ic];
        float el = pts[n + ic];

        float u = az + PI_F;                        // [0, 2pi)
        int al = __float2int_rd(u * INV_W_AZ);
        al = min(max(al, 0), NA - 1);
        float theta_a = fmaf(-(float)al, W_AZ, u);
        float w1a = __sinf(W_AZ - theta_a) * INV_SO_AZ;
        float w2a = __sinf(theta_a) * INV_SO_AZ;

        float v = el + HPI_F;                       // [0, pi]
        int q = __float2int_rd(v * INV_W_EL);
        q = min(max(q, 0), NE);
        float theta_e = fmaf(-(float)q, W_EL, v);
        float w1e = __sinf(W_EL - theta_e) * INV_SO_EL;
        float w2e = __sinf(theta_e) * INV_SO_EL;

        // pole rows appear in BOTH azimuth columns -> renormalize that weight
        float s  = w1a + w2a;
        float wx = (q == 0)  ? __fdividef(w1e, s) : w1e;
        float wy = (q == NE) ? __fdividef(w2e, s) : w2e;

        s_cf[warp][lane] = make_float4(wx * w1a, wy * w1a, wx * w2a, wy * w2a);
        my_off = (unsigned)(al * NL + q) << 8;      // byte offset of 256B column
    }
    __syncwarp();

    // ---------- Phase 2: 4 points / iteration, line-local gathers -----------
    // lane = (pi = lane>>3, fq = lane&7): point p = 4i+pi.
    // qa -> features 2fq, 2fq+1 (line 0 of column); qb -> 16+2fq, 17+2fq (line 1).
    const char* __restrict__ gq = (const char*)g_quad;
    const int pi = lane >> 3;
    const int fq = lane & 7;
    const int sx = (pi >> 1) & 1;      // chunk XOR for this writer's points
    const int sl = fq ^ sx;            // physical uint2 slot

#pragma unroll 4
    for (int i = 0; i < 8; ++i) {
        int p = 4 * i + pi;
        unsigned off = __shfl_sync(0xffffffffu, my_off, p);
        float4 cf = s_cf[warp][p];                 // 4 distinct 16B addrs: 1 wf
        const char* cp = gq + off + 16 * fq;
        uint4 qa = *(const uint4*)(cp);            // features 2fq, 2fq+1
        uint4 qb = *(const uint4*)(cp + 128);      // features 16+2fq, 17+2fq

        // compute results sequentially to keep live ranges short
        float2 la = __half22float2(*(const __half2*)&qa.x);
        float2 ra = __half22float2(*(const __half2*)&qa.y);
        float res0 = fmaf(cf.w, ra.y, fmaf(cf.z, ra.x, fmaf(cf.y, la.y, cf.x * la.x)));
        la = __half22float2(*(const __half2*)&qa.z);
        ra = __half22float2(*(const __half2*)&qa.w);
        float res1 = fmaf(cf.w, ra.y, fmaf(cf.z, ra.x, fmaf(cf.y, la.y, cf.x * la.x)));
        __half2 ha = __floats2half2_rn(res0, res1);   // feats 2fq, 2fq+1

        la = __half22float2(*(const __half2*)&qb.x);
        ra = __half22float2(*(const __half2*)&qb.y);
        res0 = fmaf(cf.w, ra.y, fmaf(cf.z, ra.x, fmaf(cf.y, la.y, cf.x * la.x)));
        la = __half22float2(*(const __half2*)&qb.z);
        ra = __half22float2(*(const __half2*)&qb.w);
        res1 = fmaf(cf.w, ra.y, fmaf(cf.z, ra.x, fmaf(cf.y, la.y, cf.x * la.x)));
        __half2 hb = __floats2half2_rn(res0, res1);   // feats 16+2fq, 17+2fq

        int row = 8 * pi + i;                          // row(p) = 8*(p&3) + (p>>2)
        s_tile[warp][row][sl] = make_uint2(*(unsigned*)&ha, *(unsigned*)&hb);
    }
    __syncwarp();

    // ---------- Phase 3: 8x LDS.64 (conflict-free) + unpack + coalesced STG -
    int ip = base + lane;
    if (ip < n) {
        const int row = 8 * (lane & 3) + (lane >> 2);
        const int x   = (lane >> 1) & 1;
        const size_t sn = (size_t)n;
        float* o = out + ip;
#pragma unroll
        for (int m = 0; m < 8; ++m) {
            uint2 v = s_tile[warp][row][m ^ x];
            float2 a = __half22float2(*(const __half2*)&v.x);  // feats 2m, 2m+1
            float2 b = __half22float2(*(const __half2*)&v.y);  // feats 16+2m, 17+2m
            o[(size_t)(2 * m)      * sn] = a.x;
            o[(size_t)(2 * m + 1)  * sn] = a.y;
            o[(size_t)(16 + 2 * m) * sn] = b.x;
            o[(size_t)(17 + 2 * m) * sn] = b.y;
        }
    }
}

extern "C" void kernel_launch(void* const* d_in, const int* in_sizes, int n_in,
                              void* d_out, int out_size) {
    const float* pts   = (const float*)d_in[0];  // (2, N)
    const float* grid  = (const float*)d_in[1];  // (32, 64, 32)
    const float* poles = (const float*)d_in[2];  // (32, 2)
    float* out = (float*)d_out;                  // (32, N)
    int n = in_sizes[0] / 2;

    prep_kernel<<<(NA * NL * FEAT + 255) / 256, 256>>>(grid, poles);
    interp_kernel<<<(n + BLK - 1) / BLK, BLK>>>(pts, out, n);
}